// round 12
// baseline (speedup 1.0000x reference)
#include <cuda_runtime.h>
#include <math.h>
#include <stdint.h>

// Problem dims
#define HH 128
#define WW 128
#define BB 8
#define DD 128
#define MM (HH*WW*BB)          // 131072 rows

typedef unsigned long long ull;

// ---------------- scratch (no cudaMalloc allowed) ----------------
__device__ float  g_inp [MM * 256];   // silu(x@W_in + b_in), interleaved re/im
__device__ float  g_gate[MM * 256];   // silu(x@W_gate + b_gate)
__device__ float  g_lam [MM * 128];   // sigmoid(x@W_lambda + b_lambda)
__device__ float2 g_acc [MM * 128];   // sum of 4 scans

static __device__ __forceinline__ float sigmoidf_(float v) {
    return 1.0f / (1.0f + __expf(-v));     // MUFU path; ~2^-21 rel err
}

// ---------------- packed fp32x2 helpers ----------------
static __device__ __forceinline__ ull pack2(float v) {
    ull r; asm("mov.b64 %0, {%1, %1};" : "=l"(r) : "f"(v)); return r;
}
static __device__ __forceinline__ void ffma2(ull &d, ull a, ull b) {
    asm("fma.rn.f32x2 %0, %1, %2, %0;" : "+l"(d) : "l"(a), "l"(b));
}
static __device__ __forceinline__ void lds2(ull &a, ull &b, unsigned addr) {
    asm volatile("ld.shared.v2.b64 {%0, %1}, [%2];" : "=l"(a), "=l"(b) : "r"(addr));
}
static __device__ __forceinline__ float2 unpack2(ull v) {
    float2 r; asm("mov.b64 {%0, %1}, %2;" : "=f"(r.x), "=f"(r.y) : "l"(v)); return r;
}

// =====================================================================
// K1: x(M x 128) @ [W_in | W_gate | W_lambda](128 x 640)  + bias + act
//     BM=128, BN=64, K=128. 512 threads (16 warps), 4x4 microtile.
//     smem = A 64KB + B 32KB = 96KB  ->  2 CTAs per SM = 32 warps/SM.
// =====================================================================
#define K1_SMEM 98304

__global__ void __launch_bounds__(512, 2)
k1_in_gemm(const float* __restrict__ x,
           const float* __restrict__ Win, const float* __restrict__ bin,
           const float* __restrict__ Wl,  const float* __restrict__ bl,
           const float* __restrict__ Wg,  const float* __restrict__ bg)
{
    extern __shared__ float sm[];
    float* As = sm;              // [128 m][128 k]
    float* Bs = sm + 128 * 128;  // [128 k][64 n]

    const int tid = threadIdx.x;
    const int nt = blockIdx.x;               // 0..9 (64-col tile)
    const int m0 = blockIdx.y * 128;

    const float* Wsrc; const float* bias; int ldn, c0;
    if (nt < 4)      { Wsrc = Win; bias = bin; ldn = 256; c0 = nt * 64; }
    else if (nt < 8) { Wsrc = Wg;  bias = bg;  ldn = 256; c0 = (nt - 4) * 64; }
    else             { Wsrc = Wl;  bias = bl;  ldn = 128; c0 = (nt - 8) * 64; }

    // ---- load A tile (coalesced float4): 4096 float4
    {
        const float4* xr = (const float4*)(x + (size_t)m0 * 128);
        float4* As4 = (float4*)As;
#pragma unroll
        for (int t = 0; t < 8; t++) As4[tid + t * 512] = xr[tid + t * 512];
    }
    // ---- load B tile (128 k x 64 n): 2048 float4
    {
        float4* Bs4 = (float4*)Bs;
#pragma unroll
        for (int t = 0; t < 4; t++) {
            int idx = tid + t * 512;
            int k = idx >> 4, n4 = idx & 15;
            Bs4[idx] = *(const float4*)&Wsrc[k * ldn + c0 + n4 * 4];
        }
    }
    __syncthreads();

    const int ty = tid >> 4;     // 0..31 -> rows ty*4
    const int tx = tid & 15;     // 0..15 -> cols tx*4
    const unsigned bs_base = (unsigned)__cvta_generic_to_shared(Bs) + tx * 16;
    const float4* As4c = (const float4*)As;

    ull acc[4][2];
#pragma unroll
    for (int i = 0; i < 4; i++) { acc[i][0] = 0ULL; acc[i][1] = 0ULL; }

#pragma unroll 4
    for (int kc = 0; kc < 32; kc++) {
        ull b[4][2];
#pragma unroll
        for (int kk = 0; kk < 4; kk++)
            lds2(b[kk][0], b[kk][1], bs_base + (unsigned)((kc * 4 + kk) * 256));
#pragma unroll
        for (int i = 0; i < 4; i++) {
            float4 a = As4c[(ty * 4 + i) * 32 + kc];
            ull a0 = pack2(a.x), a1 = pack2(a.y), a2 = pack2(a.z), a3 = pack2(a.w);
            ffma2(acc[i][0], a0, b[0][0]); ffma2(acc[i][1], a0, b[0][1]);
            ffma2(acc[i][0], a1, b[1][0]); ffma2(acc[i][1], a1, b[1][1]);
            ffma2(acc[i][0], a2, b[2][0]); ffma2(acc[i][1], a2, b[2][1]);
            ffma2(acc[i][0], a3, b[3][0]); ffma2(acc[i][1], a3, b[3][1]);
        }
    }

    // ---- epilogue: 4 rows x 4 cols per thread, float4 stores
    {
        const int nb = tx * 4;
        float4 b4 = *(const float4*)&bias[c0 + nb];
#pragma unroll
        for (int i = 0; i < 4; i++) {
            int row = m0 + ty * 4 + i;
            float v[4];
            float2 u0 = unpack2(acc[i][0]); v[0] = u0.x + b4.x; v[1] = u0.y + b4.y;
            float2 u1 = unpack2(acc[i][1]); v[2] = u1.x + b4.z; v[3] = u1.y + b4.w;
            float* dst;
            if (nt < 8) {
#pragma unroll
                for (int j = 0; j < 4; j++) v[j] = v[j] * sigmoidf_(v[j]);   // silu
                dst = (nt < 4 ? g_inp : g_gate) + (size_t)row * 256 + c0 + nb;
            } else {
#pragma unroll
                for (int j = 0; j < 4; j++) v[j] = sigmoidf_(v[j]);          // lambda
                dst = g_lam + (size_t)row * 128 + c0 + nb;
            }
            *(float4*)dst = make_float4(v[0], v[1], v[2], v[3]);
        }
    }
}

// =====================================================================
// K2: scans along H (axis 0). fwd(theta_f) writes acc; rev(theta_r) RMW.
// =====================================================================
__global__ void k2_hscan(const float* __restrict__ thf, const float* __restrict__ thr_)
{
    int idx = blockIdx.x * blockDim.x + threadIdx.x;
    int d  = idx & 127;
    int wb = idx >> 7;
    int base = wb * 128 + d;

    const float2* __restrict__ inp2 = (const float2*)g_inp;

    {
        float t = thf[d];
        float cf = cosf(t), sf = sinf(t);
        float hr = 0.f, hi = 0.f;
        int off = base;
#pragma unroll 8
        for (int h = 0; h < 128; h++, off += 131072) {
            float lam = g_lam[off];
            float2 p  = inp2[off];
            float a = lam * cf, b = lam * sf, om = 1.f - lam;
            float nr = a * hr - b * hi + om * p.x;
            float ni = a * hi + b * hr + om * p.y;
            hr = nr; hi = ni;
            g_acc[off] = make_float2(hr, hi);
        }
    }
    {
        float t = thr_[d];
        float cr = cosf(t), sr = sinf(t);
        float hr = 0.f, hi = 0.f;
        int off = base + 127 * 131072;
#pragma unroll 8
        for (int h = 0; h < 128; h++, off -= 131072) {
            float lam = g_lam[off];
            float2 p  = inp2[off];
            float a = lam * cr, b = lam * sr, om = 1.f - lam;
            float nr = a * hr - b * hi + om * p.x;
            float ni = a * hi + b * hr + om * p.y;
            hr = nr; hi = ni;
            float2 acc = g_acc[off];
            acc.x += hr; acc.y += hi;
            g_acc[off] = acc;
        }
    }
}

// =====================================================================
// K3: scans along W (axis 1). Both directions RMW into acc.
// =====================================================================
__global__ void k3_wscan(const float* __restrict__ thf, const float* __restrict__ thr_)
{
    int idx = blockIdx.x * blockDim.x + threadIdx.x;
    int d = idx & 127;
    int b = (idx >> 7) & 7;
    int h = idx >> 10;
    int base = (h * 1024 + b) * 128 + d;

    const float2* __restrict__ inp2 = (const float2*)g_inp;

    {
        float t = thf[d];
        float cf = cosf(t), sf = sinf(t);
        float hr = 0.f, hi = 0.f;
        int off = base;
#pragma unroll 8
        for (int w = 0; w < 128; w++, off += 1024) {
            float lam = g_lam[off];
            float2 p  = inp2[off];
            float a = lam * cf, bb = lam * sf, om = 1.f - lam;
            float nr = a * hr - bb * hi + om * p.x;
            float ni = a * hi + bb * hr + om * p.y;
            hr = nr; hi = ni;
            float2 acc = g_acc[off];
            acc.x += hr; acc.y += hi;
            g_acc[off] = acc;
        }
    }
    {
        float t = thr_[d];
        float cr = cosf(t), sr = sinf(t);
        float hr = 0.f, hi = 0.f;
        int off = base + 127 * 1024;
#pragma unroll 8
        for (int w = 0; w < 128; w++, off -= 1024) {
            float lam = g_lam[off];
            float2 p  = inp2[off];
            float a = lam * cr, bb = lam * sr, om = 1.f - lam;
            float nr = a * hr - bb * hi + om * p.x;
            float ni = a * hi + bb * hr + om * p.y;
            hr = nr; hi = ni;
            float2 acc = g_acc[off];
            acc.x += hr; acc.y += hi;
            g_acc[off] = acc;
        }
    }
}

// =====================================================================
// K4: LN(256)*ln_w+ln_b, *gate -> feat smem; GEMM @ W_out + b_out.
//     512 threads, 2-way split-K, 8x4 microtile, FFMA2. (round-11, 248us)
// =====================================================================
#define FLD 260
#define STG 132

__global__ void __launch_bounds__(512, 1)
k4_out_gemm(const float* __restrict__ Wout, const float* __restrict__ bout,
            const float* __restrict__ lnw,  const float* __restrict__ lnb,
            float* __restrict__ out)
{
    extern __shared__ float smf[];
    float* feat = smf;              // [64][FLD]
    float* Ws   = smf + 64 * FLD;   // [256][128]

    const int tid = threadIdx.x;
    const int m0 = blockIdx.x * 64;

    {
        float4* Ws4 = (float4*)Ws;
        const float4* W4 = (const float4*)Wout;
#pragma unroll
        for (int t = 0; t < 16; t++) Ws4[tid + t * 512] = W4[tid + t * 512];
    }

    {
        int r = tid >> 3;
        int q = tid & 7;
        int row = m0 + r;
        const float2* accp = g_acc + (size_t)row * 128;

        float sum = 0.f, ss = 0.f;
#pragma unroll
        for (int t = 0; t < 16; t++) {
            int dd = q + t * 8;
            float2 v = accp[dd];
            sum += v.x + v.y;
            ss  += v.x * v.x + v.y * v.y;
        }
        sum += __shfl_xor_sync(0xffffffffu, sum, 1);
        sum += __shfl_xor_sync(0xffffffffu, sum, 2);
        sum += __shfl_xor_sync(0xffffffffu, sum, 4);
        ss  += __shfl_xor_sync(0xffffffffu, ss, 1);
        ss  += __shfl_xor_sync(0xffffffffu, ss, 2);
        ss  += __shfl_xor_sync(0xffffffffu, ss, 4);

        float mu   = sum * (1.0f / 256.0f);
        float var  = ss * (1.0f / 256.0f) - mu * mu;
        float rstd = rsqrtf(var + 1e-5f);

        const float* gr = g_gate + (size_t)row * 256;
#pragma unroll
        for (int t = 0; t < 16; t++) {
            int dd = q + t * 8;
            float2 v = accp[dd];
            float fr = ((v.x - mu) * rstd * lnw[dd]       + lnb[dd])       * gr[dd];
            float fi = ((v.y - mu) * rstd * lnw[128 + dd] + lnb[128 + dd]) * gr[128 + dd];
            feat[r * FLD + dd]       = fr;
            feat[r * FLD + 128 + dd] = fi;
        }
    }
    __syncthreads();

    const int gid = tid >> 8;
    const int lt  = tid & 255;
    const int ty  = lt >> 5;
    const int tx  = lt & 31;
    const unsigned ws_base = (unsigned)__cvta_generic_to_shared(Ws) + tx * 16;

    ull acc[8][2];
#pragma unroll
    for (int i = 0; i < 8; i++) { acc[i][0] = 0ULL; acc[i][1] = 0ULL; }

    const int kc0 = gid * 32;
#pragma unroll 4
    for (int kq = 0; kq < 32; kq++) {
        const int kc = kc0 + kq;
        ull b[4][2];
#pragma unroll
        for (int kk = 0; kk < 4; kk++)
            lds2(b[kk][0], b[kk][1], ws_base + (unsigned)((kc * 4 + kk) * 512));
#pragma unroll
        for (int i = 0; i < 8; i++) {
            float4 a = *(const float4*)&feat[(ty * 8 + i) * FLD + kc * 4];
            ull a0 = pack2(a.x), a1 = pack2(a.y), a2 = pack2(a.z), a3 = pack2(a.w);
            ffma2(acc[i][0], a0, b[0][0]); ffma2(acc[i][1], a0, b[0][1]);
            ffma2(acc[i][0], a1, b[1][0]); ffma2(acc[i][1], a1, b[1][1]);
            ffma2(acc[i][0], a2, b[2][0]); ffma2(acc[i][1], a2, b[2][1]);
            ffma2(acc[i][0], a3, b[3][0]); ffma2(acc[i][1], a3, b[3][1]);
        }
    }
    __syncthreads();

    float* stage = smf;
    if (gid == 1) {
#pragma unroll
        for (int i = 0; i < 8; i++) {
            float2 u0 = unpack2(acc[i][0]);
            float2 u1 = unpack2(acc[i][1]);
            *(float4*)&stage[(ty * 8 + i) * STG + tx * 4] =
                make_float4(u0.x, u0.y, u1.x, u1.y);
        }
    }
    __syncthreads();

    if (gid == 0) {
        float4 b4 = *(const float4*)&bout[tx * 4];
#pragma unroll
        for (int i = 0; i < 8; i++) {
            int row = m0 + ty * 8 + i;
            float4 s = *(const float4*)&stage[(ty * 8 + i) * STG + tx * 4];
            float2 u0 = unpack2(acc[i][0]);
            float2 u1 = unpack2(acc[i][1]);
            float* dst = out + (size_t)row * 128 + tx * 4;
            *(float4*)dst = make_float4(u0.x + s.x + b4.x, u0.y + s.y + b4.y,
                                        u1.x + s.z + b4.z, u1.y + s.w + b4.w);
        }
    }
}

// =====================================================================
extern "C" void kernel_launch(void* const* d_in, const int* in_sizes, int n_in,
                              void* d_out, int out_size)
{
    const float* x    = (const float*)d_in[0];
    const float* Win  = (const float*)d_in[1];
    const float* bin  = (const float*)d_in[2];
    const float* Wl   = (const float*)d_in[3];
    const float* bl   = (const float*)d_in[4];
    const float* thf  = (const float*)d_in[5];
    const float* thr_ = (const float*)d_in[6];
    const float* Wg   = (const float*)d_in[7];
    const float* bg   = (const float*)d_in[8];
    const float* Wout = (const float*)d_in[9];
    const float* bout = (const float*)d_in[10];
    const float* lnw  = (const float*)d_in[11];
    const float* lnb  = (const float*)d_in[12];
    float* out = (float*)d_out;

    const int SM4 = (64 * FLD + 256 * 128) * 4;        // 197632
    cudaFuncSetAttribute(k1_in_gemm,  cudaFuncAttributeMaxDynamicSharedMemorySize, K1_SMEM);
    cudaFuncSetAttribute(k4_out_gemm, cudaFuncAttributeMaxDynamicSharedMemorySize, SM4);

    dim3 g1(10, MM / 128);                             // (10, 1024)
    k1_in_gemm<<<g1, 512, K1_SMEM>>>(x, Win, bin, Wl, bl, Wg, bg);

    k2_hscan<<<MM / 256, 256>>>(thf, thr_);
    k3_wscan<<<MM / 256, 256>>>(thf, thr_);

    k4_out_gemm<<<MM / 64, 512, SM4>>>(Wout, bout, lnw, lnb, out);
}

// round 13
// speedup vs baseline: 1.2365x; 1.2365x over previous
#include <cuda_runtime.h>
#include <math.h>
#include <stdint.h>

// Problem dims
#define HH 128
#define WW 128
#define BB 8
#define DD 128
#define MM (HH*WW*BB)          // 131072 rows

typedef unsigned long long ull;

// ---------------- scratch (no cudaMalloc allowed) ----------------
__device__ float  g_inp [MM * 256];   // silu(x@W_in + b_in), interleaved re/im
__device__ float  g_gate[MM * 256];   // silu(x@W_gate + b_gate)
__device__ float  g_lam [MM * 128];   // sigmoid(x@W_lambda + b_lambda)
__device__ float2 g_acc [MM * 128];   // sum of 4 scans

static __device__ __forceinline__ float sigmoidf_(float v) {
    return 1.0f / (1.0f + __expf(-v));
}

// ---------------- packed fp32x2 helpers ----------------
static __device__ __forceinline__ ull pack2(float v) {
    ull r; asm("mov.b64 %0, {%1, %1};" : "=l"(r) : "f"(v)); return r;
}
static __device__ __forceinline__ void ffma2(ull &d, ull a, ull b) {
    asm("fma.rn.f32x2 %0, %1, %2, %0;" : "+l"(d) : "l"(a), "l"(b));
}
static __device__ __forceinline__ void lds2(ull &a, ull &b, unsigned addr) {
    asm volatile("ld.shared.v2.b64 {%0, %1}, [%2];" : "=l"(a), "=l"(b) : "r"(addr));
}
static __device__ __forceinline__ float2 unpack2(ull v) {
    float2 r; asm("mov.b64 {%0, %1}, %2;" : "=f"(r.x), "=f"(r.y) : "l"(v)); return r;
}

// =====================================================================
// K1: x(M x 128) @ [W_in | W_gate | W_lambda](128 x 640)  + bias + act
//     BM=128, BN=64, K=128. 256 threads, 8x4 microtile, FFMA2.
//     96KB smem -> 2 CTAs/SM.  (round-11 config, measured 487us)
// =====================================================================
#define K1_SMEM 98304

__global__ void __launch_bounds__(256, 2)
k1_in_gemm(const float* __restrict__ x,
           const float* __restrict__ Win, const float* __restrict__ bin,
           const float* __restrict__ Wl,  const float* __restrict__ bl,
           const float* __restrict__ Wg,  const float* __restrict__ bg)
{
    extern __shared__ float sm[];
    float* As = sm;              // [128 m][128 k]
    float* Bs = sm + 128 * 128;  // [128 k][64 n]

    const int tid = threadIdx.x;
    const int nt = blockIdx.x;
    const int m0 = blockIdx.y * 128;

    const float* Wsrc; const float* bias; int ldn, c0;
    if (nt < 4)      { Wsrc = Win; bias = bin; ldn = 256; c0 = nt * 64; }
    else if (nt < 8) { Wsrc = Wg;  bias = bg;  ldn = 256; c0 = (nt - 4) * 64; }
    else             { Wsrc = Wl;  bias = bl;  ldn = 128; c0 = (nt - 8) * 64; }

    {
        const float4* xr = (const float4*)(x + (size_t)m0 * 128);
        float4* As4 = (float4*)As;
#pragma unroll
        for (int t = 0; t < 16; t++) As4[tid + t * 256] = xr[tid + t * 256];
    }
    {
        float4* Bs4 = (float4*)Bs;
#pragma unroll
        for (int t = 0; t < 8; t++) {
            int idx = tid + t * 256;
            int k = idx >> 4, n4 = idx & 15;
            Bs4[idx] = *(const float4*)&Wsrc[k * ldn + c0 + n4 * 4];
        }
    }
    __syncthreads();

    const int ty = tid >> 4;
    const int tx = tid & 15;
    const unsigned bs_base = (unsigned)__cvta_generic_to_shared(Bs) + tx * 16;
    const float4* As4c = (const float4*)As;

    ull acc[8][2];
#pragma unroll
    for (int i = 0; i < 8; i++) { acc[i][0] = 0ULL; acc[i][1] = 0ULL; }

#pragma unroll 4
    for (int kc = 0; kc < 32; kc++) {
        ull b[4][2];
#pragma unroll
        for (int kk = 0; kk < 4; kk++)
            lds2(b[kk][0], b[kk][1], bs_base + (unsigned)((kc * 4 + kk) * 256));
#pragma unroll
        for (int i = 0; i < 8; i++) {
            float4 a = As4c[(ty * 8 + i) * 32 + kc];
            ull a0 = pack2(a.x), a1 = pack2(a.y), a2 = pack2(a.z), a3 = pack2(a.w);
            ffma2(acc[i][0], a0, b[0][0]); ffma2(acc[i][1], a0, b[0][1]);
            ffma2(acc[i][0], a1, b[1][0]); ffma2(acc[i][1], a1, b[1][1]);
            ffma2(acc[i][0], a2, b[2][0]); ffma2(acc[i][1], a2, b[2][1]);
            ffma2(acc[i][0], a3, b[3][0]); ffma2(acc[i][1], a3, b[3][1]);
        }
    }

    {
        const int nb = tx * 4;
        float4 b4 = *(const float4*)&bias[c0 + nb];
#pragma unroll
        for (int i = 0; i < 8; i++) {
            int row = m0 + ty * 8 + i;
            float v[4];
            float2 u0 = unpack2(acc[i][0]); v[0] = u0.x + b4.x; v[1] = u0.y + b4.y;
            float2 u1 = unpack2(acc[i][1]); v[2] = u1.x + b4.z; v[3] = u1.y + b4.w;
            float* dst;
            if (nt < 8) {
#pragma unroll
                for (int j = 0; j < 4; j++) v[j] = v[j] * sigmoidf_(v[j]);
                dst = (nt < 4 ? g_inp : g_gate) + (size_t)row * 256 + c0 + nb;
            } else {
#pragma unroll
                for (int j = 0; j < 4; j++) v[j] = sigmoidf_(v[j]);
                dst = g_lam + (size_t)row * 128 + c0 + nb;
            }
            *(float4*)dst = make_float4(v[0], v[1], v[2], v[3]);
        }
    }
}

// =====================================================================
// Chunked parallel scan: 4 threads per (line,d), chunk = 32 steps.
// Phase 1: per-chunk transform (G,X) for fwd(theta_f) AND rev(theta_r),
//          both built in ONE ascending pass (rev composed from right).
// Phase 2: shfl prefix across the 4 chunks (lane stride 8).
// Phase 3: re-scan chunk from prefix state; fwd buffered in regs; rev
//          pass descends, sums, writes acc once (RMW only for AXIS=1).
// lane = chunk*8 + dlow; warp covers 8 d x 4 chunks of one line.
// block = 256 thr = 64 d of one line; grid = lines*2.
// =====================================================================
template<int AXIS>
__global__ void __launch_bounds__(256)
kscan2(const float* __restrict__ thf, const float* __restrict__ thr_)
{
    const int tid   = threadIdx.x;
    const int lane  = tid & 31;
    const int warp  = tid >> 5;
    const int chunk = lane >> 3;
    const int bi    = blockIdx.x;
    const int d     = (bi & 1) * 64 + warp * 8 + (lane & 7);

    size_t base; int stride;
    if (AXIS == 0) {
        int wb = bi >> 1;
        base = (size_t)wb * 128 + d;
        stride = 131072;
    } else {
        int hb = bi >> 1;
        base = ((size_t)(hb >> 3) * 1024 + (size_t)(hb & 7)) * 128 + d;
        stride = 1024;
    }

    const float2* __restrict__ inp2 = (const float2*)g_inp;

    const float tf = thf[d], tr = thr_[d];
    const float cf = cosf(tf), sf = sinf(tf);
    const float cr = cosf(tr), sr = sinf(tr);

    const size_t off0 = base + (size_t)(chunk * 32) * stride;

    // ---- Phase 1: chunk transforms
    float GfR = 1.f, GfI = 0.f, XfR = 0.f, XfI = 0.f;   // fwd (compose from left)
    float GrR = 1.f, GrI = 0.f, XrR = 0.f, XrI = 0.f;   // rev (compose from right)
#pragma unroll
    for (int i = 0; i < 32; i++) {
        size_t o = off0 + (size_t)i * stride;
        float lam = g_lam[o];
        float2 p  = inp2[o];
        float om = 1.f - lam;
        float xr = om * p.x, xi = om * p.y;
        {   // fwd: A = T(i) ∘ A : X = g*X + x ; G = g*G
            float gr = lam * cf, gi = lam * sf;
            float nXr = gr * XfR - gi * XfI + xr;
            float nXi = gr * XfI + gi * XfR + xi;
            float nGr = gr * GfR - gi * GfI;
            float nGi = gr * GfI + gi * GfR;
            XfR = nXr; XfI = nXi; GfR = nGr; GfI = nGi;
        }
        {   // rev: A = A ∘ T(i) : X = G*x + X ; G = G*g
            float gr = lam * cr, gi = lam * sr;
            float nXr = GrR * xr - GrI * xi + XrR;
            float nXi = GrR * xi + GrI * xr + XrI;
            float nGr = GrR * gr - GrI * gi;
            float nGi = GrR * gi + GrI * gr;
            XrR = nXr; XrI = nXi; GrR = nGr; GrI = nGi;
        }
    }

    // ---- Phase 2: prefix across chunks
    float hinfR, hinfI;    // fwd entering state for this chunk
    {
        float gR = GfR, gI = GfI, xR = XfR, xI = XfI;
        // step 1 (dist 8): combine with chunk-1
        float pGr = __shfl_up_sync(0xffffffffu, gR, 8);
        float pGi = __shfl_up_sync(0xffffffffu, gI, 8);
        float pXr = __shfl_up_sync(0xffffffffu, xR, 8);
        float pXi = __shfl_up_sync(0xffffffffu, xI, 8);
        if (chunk >= 1) {
            float nXr = gR * pXr - gI * pXi + xR;
            float nXi = gR * pXi + gI * pXr + xI;
            float nGr = gR * pGr - gI * pGi;
            float nGi = gR * pGi + gI * pGr;
            xR = nXr; xI = nXi; gR = nGr; gI = nGi;
        }
        // step 2 (dist 16)
        pGr = __shfl_up_sync(0xffffffffu, gR, 16);
        pGi = __shfl_up_sync(0xffffffffu, gI, 16);
        pXr = __shfl_up_sync(0xffffffffu, xR, 16);
        pXi = __shfl_up_sync(0xffffffffu, xI, 16);
        if (chunk >= 2) {
            float nXr = gR * pXr - gI * pXi + xR;
            float nXi = gR * pXi + gI * pXr + xI;
            xR = nXr; xI = nXi;
            // G not needed further
        }
        // exclusive
        pXr = __shfl_up_sync(0xffffffffu, xR, 8);
        pXi = __shfl_up_sync(0xffffffffu, xI, 8);
        hinfR = (chunk == 0) ? 0.f : pXr;
        hinfI = (chunk == 0) ? 0.f : pXi;
    }
    float hinrR, hinrI;    // rev entering state for this chunk
    {
        float gR = GrR, gI = GrI, xR = XrR, xI = XrI;
        // step 1 (dist 8 down): combine with chunk+1 (earlier in rev order)
        float pGr = __shfl_down_sync(0xffffffffu, gR, 8);
        float pGi = __shfl_down_sync(0xffffffffu, gI, 8);
        float pXr = __shfl_down_sync(0xffffffffu, xR, 8);
        float pXi = __shfl_down_sync(0xffffffffu, xI, 8);
        if (chunk <= 2) {
            float nXr = gR * pXr - gI * pXi + xR;
            float nXi = gR * pXi + gI * pXr + xI;
            float nGr = gR * pGr - gI * pGi;
            float nGi = gR * pGi + gI * pGr;
            xR = nXr; xI = nXi; gR = nGr; gI = nGi;
        }
        // step 2 (dist 16 down)
        pGr = __shfl_down_sync(0xffffffffu, gR, 16);
        pGi = __shfl_down_sync(0xffffffffu, gI, 16);
        pXr = __shfl_down_sync(0xffffffffu, xR, 16);
        pXi = __shfl_down_sync(0xffffffffu, xI, 16);
        if (chunk <= 1) {
            float nXr = gR * pXr - gI * pXi + xR;
            float nXi = gR * pXi + gI * pXr + xI;
            xR = nXr; xI = nXi;
        }
        // exclusive
        pXr = __shfl_down_sync(0xffffffffu, xR, 8);
        pXi = __shfl_down_sync(0xffffffffu, xI, 8);
        hinrR = (chunk == 3) ? 0.f : pXr;
        hinrI = (chunk == 3) ? 0.f : pXi;
    }

    // ---- Phase 3: rescan (loads hit L1), fwd buffered, rev writes
    float fR[32], fI[32];
    {
        float hr = hinfR, hi = hinfI;
#pragma unroll
        for (int i = 0; i < 32; i++) {
            size_t o = off0 + (size_t)i * stride;
            float lam = g_lam[o];
            float2 p  = inp2[o];
            float om = 1.f - lam;
            float gr = lam * cf, gi = lam * sf;
            float nr = gr * hr - gi * hi + om * p.x;
            float ni = gr * hi + gi * hr + om * p.y;
            hr = nr; hi = ni;
            fR[i] = hr; fI[i] = hi;
        }
    }
    {
        float hr = hinrR, hi = hinrI;
#pragma unroll
        for (int i = 31; i >= 0; i--) {
            size_t o = off0 + (size_t)i * stride;
            float lam = g_lam[o];
            float2 p  = inp2[o];
            float om = 1.f - lam;
            float gr = lam * cr, gi = lam * sr;
            float nr = gr * hr - gi * hi + om * p.x;
            float ni = gr * hi + gi * hr + om * p.y;
            hr = nr; hi = ni;
            float2 v = make_float2(fR[i] + hr, fI[i] + hi);
            if (AXIS == 1) {
                float2 oa = g_acc[o];
                v.x += oa.x; v.y += oa.y;
            }
            g_acc[o] = v;
        }
    }
}

// =====================================================================
// K4: LN(256)*ln_w+ln_b, *gate -> feat smem; GEMM @ W_out + b_out.
//     512 threads, 2-way split-K, 8x4 microtile, FFMA2. (round-11, 248us)
// =====================================================================
#define FLD 260
#define STG 132

__global__ void __launch_bounds__(512, 1)
k4_out_gemm(const float* __restrict__ Wout, const float* __restrict__ bout,
            const float* __restrict__ lnw,  const float* __restrict__ lnb,
            float* __restrict__ out)
{
    extern __shared__ float smf[];
    float* feat = smf;              // [64][FLD]
    float* Ws   = smf + 64 * FLD;   // [256][128]

    const int tid = threadIdx.x;
    const int m0 = blockIdx.x * 64;

    {
        float4* Ws4 = (float4*)Ws;
        const float4* W4 = (const float4*)Wout;
#pragma unroll
        for (int t = 0; t < 16; t++) Ws4[tid + t * 512] = W4[tid + t * 512];
    }

    {
        int r = tid >> 3;
        int q = tid & 7;
        int row = m0 + r;
        const float2* accp = g_acc + (size_t)row * 128;

        float sum = 0.f, ss = 0.f;
#pragma unroll
        for (int t = 0; t < 16; t++) {
            int dd = q + t * 8;
            float2 v = accp[dd];
            sum += v.x + v.y;
            ss  += v.x * v.x + v.y * v.y;
        }
        sum += __shfl_xor_sync(0xffffffffu, sum, 1);
        sum += __shfl_xor_sync(0xffffffffu, sum, 2);
        sum += __shfl_xor_sync(0xffffffffu, sum, 4);
        ss  += __shfl_xor_sync(0xffffffffu, ss, 1);
        ss  += __shfl_xor_sync(0xffffffffu, ss, 2);
        ss  += __shfl_xor_sync(0xffffffffu, ss, 4);

        float mu   = sum * (1.0f / 256.0f);
        float var  = ss * (1.0f / 256.0f) - mu * mu;
        float rstd = rsqrtf(var + 1e-5f);

        const float* gr = g_gate + (size_t)row * 256;
#pragma unroll
        for (int t = 0; t < 16; t++) {
            int dd = q + t * 8;
            float2 v = accp[dd];
            float fr = ((v.x - mu) * rstd * lnw[dd]       + lnb[dd])       * gr[dd];
            float fi = ((v.y - mu) * rstd * lnw[128 + dd] + lnb[128 + dd]) * gr[128 + dd];
            feat[r * FLD + dd]       = fr;
            feat[r * FLD + 128 + dd] = fi;
        }
    }
    __syncthreads();

    const int gid = tid >> 8;
    const int lt  = tid & 255;
    const int ty  = lt >> 5;
    const int tx  = lt & 31;
    const unsigned ws_base = (unsigned)__cvta_generic_to_shared(Ws) + tx * 16;

    ull acc[8][2];
#pragma unroll
    for (int i = 0; i < 8; i++) { acc[i][0] = 0ULL; acc[i][1] = 0ULL; }

    const int kc0 = gid * 32;
#pragma unroll 4
    for (int kq = 0; kq < 32; kq++) {
        const int kc = kc0 + kq;
        ull b[4][2];
#pragma unroll
        for (int kk = 0; kk < 4; kk++)
            lds2(b[kk][0], b[kk][1], ws_base + (unsigned)((kc * 4 + kk) * 512));
#pragma unroll
        for (int i = 0; i < 8; i++) {
            float4 a = *(const float4*)&feat[(ty * 8 + i) * FLD + kc * 4];
            ull a0 = pack2(a.x), a1 = pack2(a.y), a2 = pack2(a.z), a3 = pack2(a.w);
            ffma2(acc[i][0], a0, b[0][0]); ffma2(acc[i][1], a0, b[0][1]);
            ffma2(acc[i][0], a1, b[1][0]); ffma2(acc[i][1], a1, b[1][1]);
            ffma2(acc[i][0], a2, b[2][0]); ffma2(acc[i][1], a2, b[2][1]);
            ffma2(acc[i][0], a3, b[3][0]); ffma2(acc[i][1], a3, b[3][1]);
        }
    }
    __syncthreads();

    float* stage = smf;
    if (gid == 1) {
#pragma unroll
        for (int i = 0; i < 8; i++) {
            float2 u0 = unpack2(acc[i][0]);
            float2 u1 = unpack2(acc[i][1]);
            *(float4*)&stage[(ty * 8 + i) * STG + tx * 4] =
                make_float4(u0.x, u0.y, u1.x, u1.y);
        }
    }
    __syncthreads();

    if (gid == 0) {
        float4 b4 = *(const float4*)&bout[tx * 4];
#pragma unroll
        for (int i = 0; i < 8; i++) {
            int row = m0 + ty * 8 + i;
            float4 s = *(const float4*)&stage[(ty * 8 + i) * STG + tx * 4];
            float2 u0 = unpack2(acc[i][0]);
            float2 u1 = unpack2(acc[i][1]);
            float* dst = out + (size_t)row * 128 + tx * 4;
            *(float4*)dst = make_float4(u0.x + s.x + b4.x, u0.y + s.y + b4.y,
                                        u1.x + s.z + b4.z, u1.y + s.w + b4.w);
        }
    }
}

// =====================================================================
extern "C" void kernel_launch(void* const* d_in, const int* in_sizes, int n_in,
                              void* d_out, int out_size)
{
    const float* x    = (const float*)d_in[0];
    const float* Win  = (const float*)d_in[1];
    const float* bin  = (const float*)d_in[2];
    const float* Wl   = (const float*)d_in[3];
    const float* bl   = (const float*)d_in[4];
    const float* thf  = (const float*)d_in[5];
    const float* thr_ = (const float*)d_in[6];
    const float* Wg   = (const float*)d_in[7];
    const float* bg   = (const float*)d_in[8];
    const float* Wout = (const float*)d_in[9];
    const float* bout = (const float*)d_in[10];
    const float* lnw  = (const float*)d_in[11];
    const float* lnb  = (const float*)d_in[12];
    float* out = (float*)d_out;

    const int SM4 = (64 * FLD + 256 * 128) * 4;        // 197632
    cudaFuncSetAttribute(k1_in_gemm,  cudaFuncAttributeMaxDynamicSharedMemorySize, K1_SMEM);
    cudaFuncSetAttribute(k4_out_gemm, cudaFuncAttributeMaxDynamicSharedMemorySize, SM4);

    dim3 g1(10, MM / 128);                             // (10, 1024)
    k1_in_gemm<<<g1, 256, K1_SMEM>>>(x, Win, bin, Wl, bl, Wg, bg);

    kscan2<0><<<2048, 256>>>(thf, thr_);               // H-axis, writes acc
    kscan2<1><<<2048, 256>>>(thf, thr_);               // W-axis, RMW acc

    k4_out_gemm<<<MM / 64, 512, SM4>>>(Wout, bout, lnw, lnb, out);
}